// round 1
// baseline (speedup 1.0000x reference)
#include <cuda_runtime.h>
#include <math.h>

// Problem constants
#define B_ROWS   16384
#define IN_DIM   2048
#define N_NODES  1023
#define N_LEAVES 1024
#define OUT_DIM  512
#define TDEPTH   10

// Scratch (allocation-free: __device__ globals)
__device__ float g_P[B_ROWS * N_NODES];        // sigmoid(x@W+b)  ~67 MB
__device__ float g_probs[B_ROWS * N_LEAVES];   // leaf path probs ~67 MB
__device__ float g_partials[1024];             // per-block reg partial sums

// ---------------------------------------------------------------------------
// GEMM1: P = sigmoid(x @ W + b), fused reg-partial accumulation.
// C tile 128x128, BK=16, 256 threads, 8x8 per thread.
// Grid: (ceil(1023/128)=8, 16384/128=128)
// ---------------------------------------------------------------------------
#define BM 128
#define BN 128
#define BK 16

__global__ __launch_bounds__(256) void gemm1_kernel(
    const float* __restrict__ x, const float* __restrict__ W,
    const float* __restrict__ bias)
{
    __shared__ float As[BK][BM];   // transposed A tile
    __shared__ float Bs[BK][BN];
    __shared__ float red[256];

    const int t  = threadIdx.x;
    const int tx = t % 16;         // N direction
    const int ty = t / 16;         // M direction
    const int m0 = blockIdx.y * BM;
    const int n0 = blockIdx.x * BN;

    float acc[8][8];
    #pragma unroll
    for (int i = 0; i < 8; i++)
        #pragma unroll
        for (int j = 0; j < 8; j++) acc[i][j] = 0.f;

    for (int k0 = 0; k0 < IN_DIM; k0 += BK) {
        // Load A tile: 128 rows x 16 cols = 2048 floats = 512 float4, 2/thread
        #pragma unroll
        for (int i = 0; i < 2; i++) {
            int f    = t + i * 256;       // float4 index 0..511
            int row  = f >> 2;            // 0..127
            int kgrp = f & 3;             // 0..3 (x4 floats)
            float4 v = *reinterpret_cast<const float4*>(
                &x[(size_t)(m0 + row) * IN_DIM + k0 + kgrp * 4]);
            As[kgrp * 4 + 0][row] = v.x;
            As[kgrp * 4 + 1][row] = v.y;
            As[kgrp * 4 + 2][row] = v.z;
            As[kgrp * 4 + 3][row] = v.w;
        }
        // Load B tile: 16 rows x 128 cols, scalar (W row stride 1023 is odd)
        #pragma unroll
        for (int i = 0; i < 8; i++) {
            int f = t + i * 256;          // 0..2047
            int k = f >> 7;               // 0..15
            int n = f & 127;              // 0..127
            float v = 0.f;
            if (n0 + n < N_NODES)
                v = W[(size_t)(k0 + k) * N_NODES + n0 + n];
            Bs[k][n] = v;
        }
        __syncthreads();

        #pragma unroll
        for (int kk = 0; kk < BK; kk++) {
            float a[8], bb[8];
            #pragma unroll
            for (int i = 0; i < 8; i++) a[i]  = As[kk][ty * 8 + i];
            #pragma unroll
            for (int j = 0; j < 8; j++) bb[j] = Bs[kk][tx * 8 + j];
            #pragma unroll
            for (int i = 0; i < 8; i++)
                #pragma unroll
                for (int j = 0; j < 8; j++) acc[i][j] += a[i] * bb[j];
        }
        __syncthreads();
    }

    // Epilogue: bias, sigmoid, store P, accumulate reg contribution
    float local = 0.f;
    #pragma unroll
    for (int i = 0; i < 8; i++) {
        int m = m0 + ty * 8 + i;
        #pragma unroll
        for (int j = 0; j < 8; j++) {
            int n = n0 + tx * 8 + j;
            if (n < N_NODES) {
                float z = acc[i][j] + bias[n];
                float p = 1.f / (1.f + expf(-z));
                g_P[(size_t)m * N_NODES + n] = p;
                int d = 31 - __clz(n + 1);                   // depth 0..9
                float w = (-0.5f / (float)B_ROWS) * exp2f(-(float)d);
                local += w * logf(fmaxf(p * (1.f - p), 1e-5f));
            }
        }
    }

    // Deterministic block reduction of reg partial
    red[t] = local;
    __syncthreads();
    #pragma unroll
    for (int s = 128; s > 0; s >>= 1) {
        if (t < s) red[t] += red[t + s];
        __syncthreads();
    }
    if (t == 0)
        g_partials[blockIdx.y * gridDim.x + blockIdx.x] = red[0];
}

// ---------------------------------------------------------------------------
// probs: expand tree path products. One block per row.
// ---------------------------------------------------------------------------
__global__ __launch_bounds__(256) void probs_kernel()
{
    __shared__ float sP[N_NODES];
    const int row = blockIdx.x;
    const float* Prow = g_P + (size_t)row * N_NODES;
    for (int i = threadIdx.x; i < N_NODES; i += 256) sP[i] = Prow[i];
    __syncthreads();

    #pragma unroll
    for (int j = 0; j < 4; j++) {
        int l = j * 256 + threadIdx.x;    // leaf 0..1023
        float pr = 1.f;
        #pragma unroll
        for (int d = 0; d < TDEPTH; d++) {
            int node = (1 << d) - 1 + (l >> (TDEPTH - d));
            float p = sP[node];
            pr *= ((l >> (TDEPTH - 1 - d)) & 1) ? (1.f - p) : p;
        }
        g_probs[(size_t)row * N_LEAVES + l] = pr;
    }
}

// ---------------------------------------------------------------------------
// GEMM2: out = probs @ value. M=16384, K=1024, N=512. All aligned.
// Grid: (512/128=4, 16384/128=128)
// ---------------------------------------------------------------------------
__global__ __launch_bounds__(256) void gemm2_kernel(
    const float* __restrict__ value, float* __restrict__ out)
{
    __shared__ float As[BK][BM];
    __shared__ float Bs[BK][BN];

    const int t  = threadIdx.x;
    const int tx = t % 16;
    const int ty = t / 16;
    const int m0 = blockIdx.y * BM;
    const int n0 = blockIdx.x * BN;

    float acc[8][8];
    #pragma unroll
    for (int i = 0; i < 8; i++)
        #pragma unroll
        for (int j = 0; j < 8; j++) acc[i][j] = 0.f;

    for (int k0 = 0; k0 < N_LEAVES; k0 += BK) {
        #pragma unroll
        for (int i = 0; i < 2; i++) {
            int f    = t + i * 256;
            int row  = f >> 2;
            int kgrp = f & 3;
            float4 v = *reinterpret_cast<const float4*>(
                &g_probs[(size_t)(m0 + row) * N_LEAVES + k0 + kgrp * 4]);
            As[kgrp * 4 + 0][row] = v.x;
            As[kgrp * 4 + 1][row] = v.y;
            As[kgrp * 4 + 2][row] = v.z;
            As[kgrp * 4 + 3][row] = v.w;
        }
        // B tile: 16 rows x 128 cols = 512 float4, 2/thread (value stride 512 ok)
        #pragma unroll
        for (int i = 0; i < 2; i++) {
            int f    = t + i * 256;       // 0..511
            int k    = f >> 5;            // 0..15
            int ngrp = f & 31;            // 0..31
            float4 v = *reinterpret_cast<const float4*>(
                &value[(size_t)(k0 + k) * OUT_DIM + n0 + ngrp * 4]);
            Bs[k][ngrp * 4 + 0] = v.x;
            Bs[k][ngrp * 4 + 1] = v.y;
            Bs[k][ngrp * 4 + 2] = v.z;
            Bs[k][ngrp * 4 + 3] = v.w;
        }
        __syncthreads();

        #pragma unroll
        for (int kk = 0; kk < BK; kk++) {
            float a[8], bb[8];
            #pragma unroll
            for (int i = 0; i < 8; i++) a[i]  = As[kk][ty * 8 + i];
            #pragma unroll
            for (int j = 0; j < 8; j++) bb[j] = Bs[kk][tx * 8 + j];
            #pragma unroll
            for (int i = 0; i < 8; i++)
                #pragma unroll
                for (int j = 0; j < 8; j++) acc[i][j] += a[i] * bb[j];
        }
        __syncthreads();
    }

    #pragma unroll
    for (int i = 0; i < 8; i++) {
        int m = m0 + ty * 8 + i;
        #pragma unroll
        for (int j = 0; j < 8; j++) {
            int n = n0 + tx * 8 + j;
            out[(size_t)m * OUT_DIM + n] = acc[i][j];
        }
    }
}

// ---------------------------------------------------------------------------
// reduce_reg: deterministic fixed-order sum of 1024 partials -> scalar
// ---------------------------------------------------------------------------
__global__ __launch_bounds__(256) void reduce_reg_kernel(float* __restrict__ reg)
{
    __shared__ float red[256];
    const int t = threadIdx.x;
    float s = 0.f;
    #pragma unroll
    for (int i = 0; i < 4; i++) s += g_partials[t + i * 256];
    red[t] = s;
    __syncthreads();
    #pragma unroll
    for (int stp = 128; stp > 0; stp >>= 1) {
        if (t < stp) red[t] += red[t + stp];
        __syncthreads();
    }
    if (t == 0) *reg = red[0];
}

// ---------------------------------------------------------------------------
extern "C" void kernel_launch(void* const* d_in, const int* in_sizes, int n_in,
                              void* d_out, int out_size)
{
    const float* x     = (const float*)d_in[0];
    const float* W     = (const float*)d_in[1];
    const float* bias  = (const float*)d_in[2];
    const float* value = (const float*)d_in[3];
    float* out = (float*)d_out;

    dim3 g1((N_NODES + BN - 1) / BN, B_ROWS / BM);   // (8, 128) = 1024 blocks
    gemm1_kernel<<<g1, 256>>>(x, W, bias);

    probs_kernel<<<B_ROWS, 256>>>();

    dim3 g2(OUT_DIM / BN, B_ROWS / BM);              // (4, 128)
    gemm2_kernel<<<g2, 256>>>(value, out);

    if (out_size > B_ROWS * OUT_DIM)
        reduce_reg_kernel<<<1, 256>>>(out + (size_t)B_ROWS * OUT_DIM);
}

// round 3
// speedup vs baseline: 2.6445x; 2.6445x over previous
#include <cuda_runtime.h>
#include <cuda_bf16.h>
#include <cstdint>
#include <math.h>

// ---------------------------------------------------------------------------
// Problem constants
// ---------------------------------------------------------------------------
#define B_ROWS   16384
#define IN_DIM   2048
#define N_NODES  1023
#define N_PAD    1024
#define OUT_DIM  512
#define TDEPTH   10

// ---------------------------------------------------------------------------
// Scratch (__device__ globals; allocation-free)
// ---------------------------------------------------------------------------
__device__ __nv_bfloat16 g_xhi[B_ROWS * IN_DIM];
__device__ __nv_bfloat16 g_xlo[B_ROWS * IN_DIM];
__device__ __nv_bfloat16 g_Whi[IN_DIM * N_PAD];
__device__ __nv_bfloat16 g_Wlo[IN_DIM * N_PAD];
__device__ __nv_bfloat16 g_vhi[N_PAD * OUT_DIM];
__device__ __nv_bfloat16 g_vlo[N_PAD * OUT_DIM];
__device__ float         g_P[B_ROWS * N_PAD];
__device__ __nv_bfloat16 g_phi[B_ROWS * N_PAD];
__device__ __nv_bfloat16 g_plo[B_ROWS * N_PAD];
__device__ float         g_partials[1024];

// ---------------------------------------------------------------------------
// Inline PTX helpers (reference-output style, known-good pattern)
// ---------------------------------------------------------------------------
__device__ __forceinline__ void ldsm_x4(uint32_t& r0, uint32_t& r1,
                                        uint32_t& r2, uint32_t& r3, uint32_t addr) {
    asm volatile("ldmatrix.sync.aligned.m8n8.x4.shared.b16 {%0,%1,%2,%3},[%4];"
        : "=r"(r0), "=r"(r1), "=r"(r2), "=r"(r3) : "r"(addr));
}

__device__ __forceinline__ void ldsm_x4_trans(uint32_t& r0, uint32_t& r1,
                                              uint32_t& r2, uint32_t& r3, uint32_t addr) {
    asm volatile("ldmatrix.sync.aligned.m8n8.x4.trans.shared.b16 {%0,%1,%2,%3},[%4];"
        : "=r"(r0), "=r"(r1), "=r"(r2), "=r"(r3) : "r"(addr));
}

__device__ __forceinline__ void mma_bf16(float& c0, float& c1, float& c2, float& c3,
                                         uint32_t a0, uint32_t a1, uint32_t a2, uint32_t a3,
                                         uint32_t b0, uint32_t b1) {
    asm volatile(
        "mma.sync.aligned.m16n8k16.row.col.f32.bf16.bf16.f32 "
        "{%0,%1,%2,%3},{%4,%5,%6,%7},{%8,%9},{%0,%1,%2,%3};"
        : "+f"(c0), "+f"(c1), "+f"(c2), "+f"(c3)
        : "r"(a0), "r"(a1), "r"(a2), "r"(a3), "r"(b0), "r"(b1));
}

__device__ __forceinline__ void cp_async16(uint32_t dst, const void* src) {
    asm volatile("cp.async.cg.shared.global [%0],[%1],16;" :: "r"(dst), "l"(src));
}

// ---------------------------------------------------------------------------
// hi/lo bf16 split helpers
// ---------------------------------------------------------------------------
__device__ __forceinline__ void split1(float a, __nv_bfloat16& h, __nv_bfloat16& l) {
    h = __float2bfloat16(a);
    l = __float2bfloat16(a - __bfloat162float(h));
}

__device__ __forceinline__ void split_store4(float4 v, __nv_bfloat16* hi,
                                             __nv_bfloat16* lo, size_t base) {
    __nv_bfloat16 h0, l0, h1, l1, h2, l2, h3, l3;
    split1(v.x, h0, l0); split1(v.y, h1, l1);
    split1(v.z, h2, l2); split1(v.w, h3, l3);
    ushort4 H = make_ushort4(__bfloat16_as_ushort(h0), __bfloat16_as_ushort(h1),
                             __bfloat16_as_ushort(h2), __bfloat16_as_ushort(h3));
    ushort4 L = make_ushort4(__bfloat16_as_ushort(l0), __bfloat16_as_ushort(l1),
                             __bfloat16_as_ushort(l2), __bfloat16_as_ushort(l3));
    *reinterpret_cast<ushort4*>(hi + base) = H;
    *reinterpret_cast<ushort4*>(lo + base) = L;
}

// ---------------------------------------------------------------------------
// Conversion kernels
// ---------------------------------------------------------------------------
__global__ __launch_bounds__(256) void conv_x_kernel(const float* __restrict__ x) {
    size_t i = (size_t)blockIdx.x * 256 + threadIdx.x;   // float4 index
    float4 v = reinterpret_cast<const float4*>(x)[i];
    split_store4(v, g_xhi, g_xlo, i * 4);
}

__global__ __launch_bounds__(256) void conv_v_kernel(const float* __restrict__ value) {
    size_t i = (size_t)blockIdx.x * 256 + threadIdx.x;
    float4 v = reinterpret_cast<const float4*>(value)[i];
    split_store4(v, g_vhi, g_vlo, i * 4);
}

__global__ __launch_bounds__(256) void conv_W_kernel(const float* __restrict__ W) {
    int idx = blockIdx.x * 256 + threadIdx.x;            // over IN_DIM * N_PAD
    int k = idx >> 10, n = idx & 1023;
    float a = (n < N_NODES) ? W[(size_t)k * N_NODES + n] : 0.f;
    __nv_bfloat16 h, l;
    split1(a, h, l);
    g_Whi[idx] = h;
    g_Wlo[idx] = l;
}

// ---------------------------------------------------------------------------
// bf16 tensor-core GEMM, 3-segment hi/lo split along K.
// Tile 128x128, BK=32, 256 threads, cp.async double-buffered.
// ---------------------------------------------------------------------------
#define BM 128
#define BN 128
#define BK 32
#define ASW 40                 // As row stride in halves (80B: conflict-free ldsm)
#define BSW 136                // Bs row stride in halves (272B)
#define ASTAGE (BM * ASW)      // 5120 halves
#define BSTAGE (BK * BSW)      // 4352 halves

template<int KH, bool EPI>
__device__ __forceinline__ void mma_gemm_body(
    const __nv_bfloat16* __restrict__ Ah, const __nv_bfloat16* __restrict__ Al, int astr,
    const __nv_bfloat16* __restrict__ Bh, const __nv_bfloat16* __restrict__ Bl, int bstr,
    const float* __restrict__ bias, float* __restrict__ out, int ostr, int nvalid)
{
    __shared__ __nv_bfloat16 As[2 * ASTAGE];
    __shared__ __nv_bfloat16 Bs[2 * BSTAGE];
    __shared__ float red[256];

    const int t    = threadIdx.x;
    const int lane = t & 31;
    const int wid  = t >> 5;
    const int wm   = wid & 1;       // 2 warps in M
    const int wn   = wid >> 1;      // 4 warps in N
    const int m0   = blockIdx.y * BM;
    const int n0   = blockIdx.x * BN;

    float acc[4][4][4];
    #pragma unroll
    for (int i = 0; i < 4; i++)
        #pragma unroll
        for (int j = 0; j < 4; j++)
            #pragma unroll
            for (int e = 0; e < 4; e++) acc[i][j][e] = 0.f;

    // ldmatrix per-lane base offsets
    const int lr = lane & 15;
    const int lh = lane >> 4;
    const uint32_t sA = (uint32_t)__cvta_generic_to_shared(As);
    const uint32_t sB = (uint32_t)__cvta_generic_to_shared(Bs);
    const uint32_t aoff = sA + (uint32_t)(((wm * 64 + lr) * ASW + lh * 8) * 2);
    const uint32_t boff = sB + (uint32_t)((lr * BSW + wn * 32 + lh * 8) * 2);

    // global->shared cp.async lane mapping
    const int aR = t >> 2, aQ = t & 3;    // A: rows aR, aR+64; 8-half chunk aQ
    const int bK = t >> 4, bQ = t & 15;   // B: k rows bK, bK+16; chunk bQ

    const int iters = 3 * (KH / BK);

    int buf = 0;

    // ---- stage 0 fetch
    {
        const __nv_bfloat16* Asrc = Ah;
        const __nv_bfloat16* Bsrc = Bh;
        #pragma unroll
        for (int i = 0; i < 2; i++) {
            const __nv_bfloat16* src = Asrc + (size_t)(m0 + aR + i * 64) * astr + aQ * 8;
            uint32_t dst = sA + (uint32_t)(((aR + i * 64) * ASW + aQ * 8) * 2);
            cp_async16(dst, src);
        }
        #pragma unroll
        for (int i = 0; i < 2; i++) {
            const __nv_bfloat16* src = Bsrc + (size_t)(bK + i * 16) * bstr + n0 + bQ * 8;
            uint32_t dst = sB + (uint32_t)(((bK + i * 16) * BSW + bQ * 8) * 2);
            cp_async16(dst, src);
        }
        asm volatile("cp.async.commit_group;");
    }
    asm volatile("cp.async.wait_group 0;");
    __syncthreads();

    for (int it = 0; it < iters; it++) {
        // prefetch next stage
        if (it + 1 < iters) {
            const int nit  = it + 1;
            const int seg  = nit % 3;
            const int kk   = (nit / 3) * BK;
            const int nbuf = buf ^ 1;
            const __nv_bfloat16* Asrc = (seg == 2) ? Al : Ah;   // hi, hi, lo
            const __nv_bfloat16* Bsrc = (seg == 1) ? Bl : Bh;   // hi, lo, hi
            #pragma unroll
            for (int i = 0; i < 2; i++) {
                const __nv_bfloat16* src =
                    Asrc + (size_t)(m0 + aR + i * 64) * astr + kk + aQ * 8;
                uint32_t dst =
                    sA + (uint32_t)((nbuf * ASTAGE + (aR + i * 64) * ASW + aQ * 8) * 2);
                cp_async16(dst, src);
            }
            #pragma unroll
            for (int i = 0; i < 2; i++) {
                const __nv_bfloat16* src =
                    Bsrc + (size_t)(kk + bK + i * 16) * bstr + n0 + bQ * 8;
                uint32_t dst =
                    sB + (uint32_t)((nbuf * BSTAGE + (bK + i * 16) * BSW + bQ * 8) * 2);
                cp_async16(dst, src);
            }
            asm volatile("cp.async.commit_group;");
        }

        const uint32_t abase = aoff + (uint32_t)(buf * ASTAGE * 2);
        const uint32_t bbase = boff + (uint32_t)(buf * BSTAGE * 2);

        #pragma unroll
        for (int ks = 0; ks < 2; ks++) {
            uint32_t ar0[4], ar1[4], ar2[4], ar3[4];
            uint32_t br0[2], br1[2], br2[2], br3[2];
            #pragma unroll
            for (int mt = 0; mt < 4; mt++) {
                uint32_t ad = abase + (uint32_t)((mt * 16 * ASW + ks * 16) * 2);
                ldsm_x4(ar0[mt], ar1[mt], ar2[mt], ar3[mt], ad);
            }
            #pragma unroll
            for (int np = 0; np < 2; np++) {
                uint32_t bd = bbase + (uint32_t)((ks * 16 * BSW + np * 16) * 2);
                ldsm_x4_trans(br0[np], br1[np], br2[np], br3[np], bd);
            }
            #pragma unroll
            for (int mt = 0; mt < 4; mt++) {
                #pragma unroll
                for (int np = 0; np < 2; np++) {
                    mma_bf16(acc[mt][np * 2 + 0][0], acc[mt][np * 2 + 0][1],
                             acc[mt][np * 2 + 0][2], acc[mt][np * 2 + 0][3],
                             ar0[mt], ar1[mt], ar2[mt], ar3[mt],
                             br0[np], br1[np]);
                    mma_bf16(acc[mt][np * 2 + 1][0], acc[mt][np * 2 + 1][1],
                             acc[mt][np * 2 + 1][2], acc[mt][np * 2 + 1][3],
                             ar0[mt], ar1[mt], ar2[mt], ar3[mt],
                             br2[np], br3[np]);
                }
            }
        }

        if (it + 1 < iters) asm volatile("cp.async.wait_group 0;");
        __syncthreads();
        buf ^= 1;
    }

    // Epilogue
    float local = 0.f;
    #pragma unroll
    for (int mt = 0; mt < 4; mt++) {
        const int r = m0 + wm * 64 + mt * 16 + (lane >> 2);
        #pragma unroll
        for (int nt = 0; nt < 4; nt++) {
            const int c = n0 + wn * 32 + nt * 8 + ((lane & 3) << 1);
            #pragma unroll
            for (int half = 0; half < 2; half++) {
                const int row = r + half * 8;
                const float v0 = acc[mt][nt][half * 2 + 0];
                const float v1 = acc[mt][nt][half * 2 + 1];
                if (EPI) {
                    float z0 = v0 + bias[c];
                    float p0 = 1.f / (1.f + expf(-z0));
                    int d0 = 31 - __clz(c + 1);
                    local += (-0.5f / (float)B_ROWS) * exp2f(-(float)d0)
                             * logf(fmaxf(p0 * (1.f - p0), 1e-5f));
                    if (c + 1 < nvalid) {
                        float z1 = v1 + bias[c + 1];
                        float p1 = 1.f / (1.f + expf(-z1));
                        int d1 = 31 - __clz(c + 2);
                        local += (-0.5f / (float)B_ROWS) * exp2f(-(float)d1)
                                 * logf(fmaxf(p1 * (1.f - p1), 1e-5f));
                        *reinterpret_cast<float2*>(out + (size_t)row * ostr + c)
                            = make_float2(p0, p1);
                    } else {
                        out[(size_t)row * ostr + c] = p0;
                    }
                } else {
                    *reinterpret_cast<float2*>(out + (size_t)row * ostr + c)
                        = make_float2(v0, v1);
                }
            }
        }
    }

    if (EPI) {
        red[t] = local;
        __syncthreads();
        #pragma unroll
        for (int s = 128; s > 0; s >>= 1) {
            if (t < s) red[t] += red[t + s];
            __syncthreads();
        }
        if (t == 0)
            g_partials[blockIdx.y * gridDim.x + blockIdx.x] = red[0];
    }
}

__global__ __launch_bounds__(256, 2) void gemm1_mma(const float* __restrict__ bias) {
    mma_gemm_body<IN_DIM, true>(g_xhi, g_xlo, IN_DIM,
                                g_Whi, g_Wlo, N_PAD,
                                bias, g_P, N_PAD, N_NODES);
}

__global__ __launch_bounds__(256, 2) void gemm2_mma(float* __restrict__ out) {
    mma_gemm_body<N_PAD, false>(g_phi, g_plo, N_PAD,
                                g_vhi, g_vlo, OUT_DIM,
                                nullptr, out, OUT_DIM, OUT_DIM);
}

// ---------------------------------------------------------------------------
// probs: expand tree path products, write bf16 hi/lo for GEMM2.
// ---------------------------------------------------------------------------
__global__ __launch_bounds__(256) void probs_kernel() {
    __shared__ float sP[N_NODES];
    const int row = blockIdx.x;
    const float* Prow = g_P + (size_t)row * N_PAD;
    for (int i = threadIdx.x; i < N_NODES; i += 256) sP[i] = Prow[i];
    __syncthreads();

    #pragma unroll
    for (int j = 0; j < 4; j++) {
        int l = j * 256 + threadIdx.x;
        float pr = 1.f;
        #pragma unroll
        for (int d = 0; d < TDEPTH; d++) {
            int node = (1 << d) - 1 + (l >> (TDEPTH - d));
            float p = sP[node];
            pr *= ((l >> (TDEPTH - 1 - d)) & 1) ? (1.f - p) : p;
        }
        __nv_bfloat16 h, lo;
        split1(pr, h, lo);
        g_phi[(size_t)row * N_PAD + l] = h;
        g_plo[(size_t)row * N_PAD + l] = lo;
    }
}

// ---------------------------------------------------------------------------
// reduce_reg: deterministic fixed-order sum of 1024 partials -> scalar
// ---------------------------------------------------------------------------
__global__ __launch_bounds__(256) void reduce_reg_kernel(float* __restrict__ reg) {
    __shared__ float red[256];
    const int t = threadIdx.x;
    float s = 0.f;
    #pragma unroll
    for (int i = 0; i < 4; i++) s += g_partials[t + i * 256];
    red[t] = s;
    __syncthreads();
    #pragma unroll
    for (int stp = 128; stp > 0; stp >>= 1) {
        if (t < stp) red[t] += red[t + stp];
        __syncthreads();
    }
    if (t == 0) *reg = red[0];
}

// ---------------------------------------------------------------------------
extern "C" void kernel_launch(void* const* d_in, const int* in_sizes, int n_in,
                              void* d_out, int out_size)
{
    const float* x     = (const float*)d_in[0];
    const float* W     = (const float*)d_in[1];
    const float* bias  = (const float*)d_in[2];
    const float* value = (const float*)d_in[3];
    float* out = (float*)d_out;

    conv_x_kernel<<<(B_ROWS * IN_DIM) / 4 / 256, 256>>>(x);
    conv_W_kernel<<<(IN_DIM * N_PAD) / 256, 256>>>(W);
    conv_v_kernel<<<(N_PAD * OUT_DIM) / 4 / 256, 256>>>(value);

    dim3 g1(N_PAD / BN, B_ROWS / BM);        // (8, 128)
    gemm1_mma<<<g1, 256>>>(bias);

    probs_kernel<<<B_ROWS, 256>>>();

    dim3 g2(OUT_DIM / BN, B_ROWS / BM);      // (4, 128)
    gemm2_mma<<<g2, 256>>>(out);

    if (out_size > B_ROWS * OUT_DIM)
        reduce_reg_kernel<<<1, 256>>>(out + (size_t)B_ROWS * OUT_DIM);
}

// round 6
// speedup vs baseline: 2.7790x; 1.0509x over previous
#include <cuda_runtime.h>
#include <cuda_bf16.h>
#include <cstdint>
#include <math.h>

// ---------------------------------------------------------------------------
// Problem constants
// ---------------------------------------------------------------------------
#define B_ROWS   16384
#define IN_DIM   2048
#define N_NODES  1023
#define N_PAD    1024
#define OUT_DIM  512
#define TDEPTH   10

// ---------------------------------------------------------------------------
// Scratch (__device__ globals; allocation-free)
// ---------------------------------------------------------------------------
__device__ __nv_bfloat16 g_xhi[B_ROWS * IN_DIM];
__device__ __nv_bfloat16 g_xlo[B_ROWS * IN_DIM];
__device__ __nv_bfloat16 g_Whi[IN_DIM * N_PAD];     // [k][n]
__device__ __nv_bfloat16 g_Wlo[IN_DIM * N_PAD];
__device__ __nv_bfloat16 g_vhi[N_PAD * OUT_DIM];    // [k][n]
__device__ __nv_bfloat16 g_vlo[N_PAD * OUT_DIM];
__device__ float         g_P[B_ROWS * N_PAD];
__device__ __nv_bfloat16 g_phi[B_ROWS * N_PAD];
__device__ __nv_bfloat16 g_plo[B_ROWS * N_PAD];
__device__ float         g_partials[1024];

// ---------------------------------------------------------------------------
// Inline PTX helpers
// ---------------------------------------------------------------------------
__device__ __forceinline__ void ldsm_x4(uint32_t& r0, uint32_t& r1,
                                        uint32_t& r2, uint32_t& r3, uint32_t addr) {
    asm volatile("ldmatrix.sync.aligned.m8n8.x4.shared.b16 {%0,%1,%2,%3},[%4];"
        : "=r"(r0), "=r"(r1), "=r"(r2), "=r"(r3) : "r"(addr));
}

__device__ __forceinline__ void ldsm_x4_trans(uint32_t& r0, uint32_t& r1,
                                              uint32_t& r2, uint32_t& r3, uint32_t addr) {
    asm volatile("ldmatrix.sync.aligned.m8n8.x4.trans.shared.b16 {%0,%1,%2,%3},[%4];"
        : "=r"(r0), "=r"(r1), "=r"(r2), "=r"(r3) : "r"(addr));
}

__device__ __forceinline__ void mma_bf16(float& c0, float& c1, float& c2, float& c3,
                                         uint32_t a0, uint32_t a1, uint32_t a2, uint32_t a3,
                                         uint32_t b0, uint32_t b1) {
    asm volatile(
        "mma.sync.aligned.m16n8k16.row.col.f32.bf16.bf16.f32 "
        "{%0,%1,%2,%3},{%4,%5,%6,%7},{%8,%9},{%0,%1,%2,%3};"
        : "+f"(c0), "+f"(c1), "+f"(c2), "+f"(c3)
        : "r"(a0), "r"(a1), "r"(a2), "r"(a3), "r"(b0), "r"(b1));
}

__device__ __forceinline__ void cp_async16(uint32_t dst, const void* src) {
    asm volatile("cp.async.cg.shared.global [%0],[%1],16;" :: "r"(dst), "l"(src));
}

__device__ __forceinline__ float rcp_approx(float x) {
    float r;
    asm("rcp.approx.f32 %0, %1;" : "=f"(r) : "f"(x));
    return r;
}

// ---------------------------------------------------------------------------
// hi/lo bf16 split helpers
// ---------------------------------------------------------------------------
__device__ __forceinline__ void split1(float a, __nv_bfloat16& h, __nv_bfloat16& l) {
    h = __float2bfloat16(a);
    l = __float2bfloat16(a - __bfloat162float(h));
}

__device__ __forceinline__ void split_store4(float4 v, __nv_bfloat16* hi,
                                             __nv_bfloat16* lo, size_t base) {
    __nv_bfloat16 h0, l0, h1, l1, h2, l2, h3, l3;
    split1(v.x, h0, l0); split1(v.y, h1, l1);
    split1(v.z, h2, l2); split1(v.w, h3, l3);
    ushort4 H = make_ushort4(__bfloat16_as_ushort(h0), __bfloat16_as_ushort(h1),
                             __bfloat16_as_ushort(h2), __bfloat16_as_ushort(h3));
    ushort4 L = make_ushort4(__bfloat16_as_ushort(l0), __bfloat16_as_ushort(l1),
                             __bfloat16_as_ushort(l2), __bfloat16_as_ushort(l3));
    *reinterpret_cast<ushort4*>(hi + base) = H;
    *reinterpret_cast<ushort4*>(lo + base) = L;
}

// ---------------------------------------------------------------------------
// Conversion kernels
// ---------------------------------------------------------------------------
__global__ __launch_bounds__(256) void conv_x_kernel(const float* __restrict__ x) {
    size_t i = (size_t)blockIdx.x * 256 + threadIdx.x;
    float4 v = reinterpret_cast<const float4*>(x)[i];
    split_store4(v, g_xhi, g_xlo, i * 4);
}

__global__ __launch_bounds__(256) void conv_v_kernel(const float* __restrict__ value) {
    size_t i = (size_t)blockIdx.x * 256 + threadIdx.x;
    float4 v = reinterpret_cast<const float4*>(value)[i];
    split_store4(v, g_vhi, g_vlo, i * 4);
}

__global__ __launch_bounds__(256) void conv_W_kernel(const float* __restrict__ W) {
    int idx = blockIdx.x * 256 + threadIdx.x;            // over IN_DIM * N_PAD
    int k = idx >> 10, n = idx & 1023;
    float a = (n < N_NODES) ? W[(size_t)k * N_NODES + n] : 0.f;
    __nv_bfloat16 h, l;
    split1(a, h, l);
    g_Whi[idx] = h;
    g_Wlo[idx] = l;
}

// ---------------------------------------------------------------------------
// bf16 mma.sync GEMM, 3-segment hi/lo split along K.
// Tile 128x128, BK=32, 256 threads, cp.async 3-stage ring (dynamic smem).
// ---------------------------------------------------------------------------
#define BM 128
#define BN 128
#define BK 32
#define ASW 40                 // As row stride in halves (80B: conflict-free ldsm)
#define BSW 136                // Bs row stride in halves (272B)
#define ASTAGE (BM * ASW)      // 5120 halves
#define BSTAGE (BK * BSW)      // 4352 halves
#define NSTAGE 3
#define AS_OFF 0
#define BS_OFF (NSTAGE * ASTAGE * 2)                 // 30720 B
#define RED_OFF (BS_OFF + NSTAGE * BSTAGE * 2)       // 56832 B
#define SMEM_DYN (RED_OFF + 256 * 4)                 // 57856 B

// weight = 2^{-depth(node)} via exponent bits; depth = 31-clz(n+1)
__device__ __forceinline__ float col_weight(int c) {
    int d = 31 - __clz(c + 1);
    return __uint_as_float((uint32_t)(127 - d) << 23);
}

template<int KH, bool EPI>
__device__ __forceinline__ void mma_gemm_body(
    const __nv_bfloat16* __restrict__ Ah, const __nv_bfloat16* __restrict__ Al, int astr,
    const __nv_bfloat16* __restrict__ Bh, const __nv_bfloat16* __restrict__ Bl, int bstr,
    const float* __restrict__ bias, float* __restrict__ out, int ostr)
{
    extern __shared__ char smem[];
    uint32_t sA, sB;
    {
        uint32_t sbase;
        asm("{ .reg .u64 t; cvta.to.shared.u64 t, %1; cvt.u32.u64 %0, t; }"
            : "=r"(sbase) : "l"(smem));
        sA = sbase + AS_OFF;
        sB = sbase + BS_OFF;
    }
    float* red = reinterpret_cast<float*>(smem + RED_OFF);

    const int t    = threadIdx.x;
    const int lane = t & 31;
    const int wid  = t >> 5;
    const int wm   = wid & 1;       // 2 warps in M
    const int wn   = wid >> 1;      // 4 warps in N
    const int m0   = blockIdx.y * BM;
    const int n0   = blockIdx.x * BN;

    float acc[4][4][4];
    #pragma unroll
    for (int i = 0; i < 4; i++)
        #pragma unroll
        for (int j = 0; j < 4; j++)
            #pragma unroll
            for (int e = 0; e < 4; e++) acc[i][j][e] = 0.f;

    const int lr = lane & 15;
    const int lh = lane >> 4;
    const uint32_t aoff = sA + (uint32_t)(((wm * 64 + lr) * ASW + lh * 8) * 2);
    const uint32_t boff = sB + (uint32_t)((lr * BSW + wn * 32 + lh * 8) * 2);

    const int aR = t >> 2, aQ = t & 3;    // A rows aR, aR+64; 8-half chunk aQ
    const int bK = t >> 4, bQ = t & 15;   // B k-rows bK, bK+16; chunk bQ

    const int iters = 3 * (KH / BK);

    auto load_stage = [&](int grp, int slot) {
        const int seg = grp % 3;
        const int kk  = (grp / 3) * BK;
        const __nv_bfloat16* Asrc = (seg == 2) ? Al : Ah;   // hi, hi, lo
        const __nv_bfloat16* Bsrc = (seg == 1) ? Bl : Bh;   // hi, lo, hi
        #pragma unroll
        for (int i = 0; i < 2; i++) {
            const __nv_bfloat16* src = Asrc + (size_t)(m0 + aR + i * 64) * astr + kk + aQ * 8;
            uint32_t dst = sA + (uint32_t)((slot * ASTAGE + (aR + i * 64) * ASW + aQ * 8) * 2);
            cp_async16(dst, src);
        }
        #pragma unroll
        for (int i = 0; i < 2; i++) {
            const __nv_bfloat16* src = Bsrc + (size_t)(kk + bK + i * 16) * bstr + n0 + bQ * 8;
            uint32_t dst = sB + (uint32_t)((slot * BSTAGE + (bK + i * 16) * BSW + bQ * 8) * 2);
            cp_async16(dst, src);
        }
        asm volatile("cp.async.commit_group;");
    };

    // prologue: 2 stages in flight
    load_stage(0, 0);
    load_stage(1, 1);

    for (int it = 0; it < iters; it++) {
        if (it + 1 < iters) asm volatile("cp.async.wait_group 1;");
        else                asm volatile("cp.async.wait_group 0;");
        __syncthreads();
        if (it + 2 < iters) load_stage(it + 2, (it + 2) % NSTAGE);

        const int buf = it % NSTAGE;
        const uint32_t abase = aoff + (uint32_t)(buf * ASTAGE * 2);
        const uint32_t bbase = boff + (uint32_t)(buf * BSTAGE * 2);

        #pragma unroll
        for (int ks = 0; ks < 2; ks++) {
            uint32_t ar0[4], ar1[4], ar2[4], ar3[4];
            uint32_t br0[2], br1[2], br2[2], br3[2];
            #pragma unroll
            for (int mt = 0; mt < 4; mt++) {
                uint32_t ad = abase + (uint32_t)((mt * 16 * ASW + ks * 16) * 2);
                ldsm_x4(ar0[mt], ar1[mt], ar2[mt], ar3[mt], ad);
            }
            #pragma unroll
            for (int np = 0; np < 2; np++) {
                uint32_t bd = bbase + (uint32_t)((ks * 16 * BSW + np * 16) * 2);
                ldsm_x4_trans(br0[np], br1[np], br2[np], br3[np], bd);
            }
            #pragma unroll
            for (int mt = 0; mt < 4; mt++) {
                #pragma unroll
                for (int np = 0; np < 2; np++) {
                    mma_bf16(acc[mt][np * 2 + 0][0], acc[mt][np * 2 + 0][1],
                             acc[mt][np * 2 + 0][2], acc[mt][np * 2 + 0][3],
                             ar0[mt], ar1[mt], ar2[mt], ar3[mt],
                             br0[np], br1[np]);
                    mma_bf16(acc[mt][np * 2 + 1][0], acc[mt][np * 2 + 1][1],
                             acc[mt][np * 2 + 1][2], acc[mt][np * 2 + 1][3],
                             ar0[mt], ar1[mt], ar2[mt], ar3[mt],
                             br2[np], br3[np]);
                }
            }
        }
    }

    // ---------------- Epilogue ----------------
    float S = 0.f;
    #pragma unroll
    for (int mt = 0; mt < 4; mt++) {
        const int r0 = m0 + wm * 64 + mt * 16 + (lane >> 2);
        const int r1 = r0 + 8;
        #pragma unroll
        for (int nt = 0; nt < 4; nt++) {
            const int c = n0 + wn * 32 + nt * 8 + ((lane & 3) << 1);
            if (EPI) {
                const bool ok1 = (c + 1) < N_NODES;            // c <= 1022 always valid
                const float b0 = bias[c];
                const float b1 = ok1 ? bias[c + 1] : 0.f;
                float z00 = acc[mt][nt][0] + b0, z01 = acc[mt][nt][1] + b1;
                float z10 = acc[mt][nt][2] + b0, z11 = acc[mt][nt][3] + b1;
                // sigmoid via EX2 + 4-way batched reciprocal + Newton refine
                float q00 = 1.f + __expf(-z00), q01 = 1.f + __expf(-z01);
                float q10 = 1.f + __expf(-z10), q11 = 1.f + __expf(-z11);
                float u0 = q00 * q01, u1 = q10 * q11;
                float rr = rcp_approx(u0 * u1);
                float ru0 = rr * u1, ru1 = rr * u0;            // ~1/u0, ~1/u1
                float p00 = ru0 * q01, p01 = ru0 * q00;
                float p10 = ru1 * q11, p11 = ru1 * q10;
                p00 = p00 * (2.f - q00 * p00);
                p01 = p01 * (2.f - q01 * p01);
                p10 = p10 * (2.f - q10 * p10);
                p11 = p11 * (2.f - q11 * p11);
                *reinterpret_cast<float2*>(out + (size_t)r0 * ostr + c) = make_float2(p00, p01);
                *reinterpret_cast<float2*>(out + (size_t)r1 * ostr + c) = make_float2(p10, p11);
                // reg: w * log(max(p(1-p),1e-5)); rows share column weight
                float v00 = fmaxf(fmaf(-p00, p00, p00), 1e-5f);
                float v01 = fmaxf(fmaf(-p01, p01, p01), 1e-5f);
                float v10 = fmaxf(fmaf(-p10, p10, p10), 1e-5f);
                float v11 = fmaxf(fmaf(-p11, p11, p11), 1e-5f);
                float w0 = col_weight(c);
                float w1 = ok1 ? col_weight(c + 1) : 0.f;
                float va = v00 * v10;                      // column c (2 rows)
                float vb = ok1 ? (v01 * v11) : 1.f;        // column c+1
                if (w0 == w1) {
                    S = fmaf(w0, __logf(va * vb), S);
                } else {
                    S = fmaf(w0, __logf(va), S);
                    if (w1 != 0.f) S = fmaf(w1, __logf(vb), S);
                }
            } else {
                *reinterpret_cast<float2*>(out + (size_t)r0 * ostr + c)
                    = make_float2(acc[mt][nt][0], acc[mt][nt][1]);
                *reinterpret_cast<float2*>(out + (size_t)r1 * ostr + c)
                    = make_float2(acc[mt][nt][2], acc[mt][nt][3]);
            }
        }
    }

    if (EPI) {
        red[t] = S;
        __syncthreads();
        #pragma unroll
        for (int s = 128; s > 0; s >>= 1) {
            if (t < s) red[t] += red[t + s];
            __syncthreads();
        }
        if (t == 0)
            g_partials[blockIdx.y * gridDim.x + blockIdx.x]
                = red[0] * (-0.5f / (float)B_ROWS);
    }
}

__global__ __launch_bounds__(256, 2) void gemm1_mma(const float* __restrict__ bias) {
    mma_gemm_body<IN_DIM, true>(g_xhi, g_xlo, IN_DIM,
                                g_Whi, g_Wlo, N_PAD,
                                bias, g_P, N_PAD);
}

__global__ __launch_bounds__(256, 2) void gemm2_mma(float* __restrict__ out) {
    mma_gemm_body<N_PAD, false>(g_phi, g_plo, N_PAD,
                                g_vhi, g_vlo, OUT_DIM,
                                nullptr, out, OUT_DIM);
}

// ---------------------------------------------------------------------------
// probs: expand tree path products, write bf16 hi/lo for GEMM2.
// ---------------------------------------------------------------------------
__global__ __launch_bounds__(256) void probs_kernel() {
    __shared__ float sP[N_NODES];
    const int row = blockIdx.x;
    const float* Prow = g_P + (size_t)row * N_PAD;
    for (int i = threadIdx.x; i < N_NODES; i += 256) sP[i] = Prow[i];
    __syncthreads();

    #pragma unroll
    for (int j = 0; j < 4; j++) {
        int l = j * 256 + threadIdx.x;
        float pr = 1.f;
        #pragma unroll
        for (int d = 0; d < TDEPTH; d++) {
            int node = (1 << d) - 1 + (l >> (TDEPTH - d));
            float p = sP[node];
            pr *= ((l >> (TDEPTH - 1 - d)) & 1) ? (1.f - p) : p;
        }
        __nv_bfloat16 h, lo;
        split1(pr, h, lo);
        g_phi[(size_t)row * N_PAD + l] = h;
        g_plo[(size_t)row * N_PAD + l] = lo;
    }
}

// ---------------------------------------------------------------------------
// reduce_reg: deterministic fixed-order sum of 1024 partials -> scalar
// ---------------------------------------------------------------------------
__global__ __launch_bounds__(256) void reduce_reg_kernel(float* __restrict__ reg) {
    __shared__ float red[256];
    const int t = threadIdx.x;
    red[t] = (g_partials[t] + g_partials[t + 256])
           + (g_partials[t + 512] + g_partials[t + 768]);
    __syncthreads();
    #pragma unroll
    for (int stp = 128; stp > 0; stp >>= 1) {
        if (t < stp) red[t] += red[t + stp];
        __syncthreads();
    }
    if (t == 0) *reg = red[0];
}

// ---------------------------------------------------------------------------
extern "C" void kernel_launch(void* const* d_in, const int* in_sizes, int n_in,
                              void* d_out, int out_size)
{
    const float* x     = (const float*)d_in[0];
    const float* W     = (const float*)d_in[1];
    const float* bias  = (const float*)d_in[2];
    const float* value = (const float*)d_in[3];
    float* out = (float*)d_out;

    cudaFuncSetAttribute(gemm1_mma, cudaFuncAttributeMaxDynamicSharedMemorySize, SMEM_DYN);
    cudaFuncSetAttribute(gemm2_mma, cudaFuncAttributeMaxDynamicSharedMemorySize, SMEM_DYN);

    conv_x_kernel<<<(B_ROWS * IN_DIM) / 4 / 256, 256>>>(x);
    conv_W_kernel<<<(IN_DIM * N_PAD) / 256, 256>>>(W);
    conv_v_kernel<<<(N_PAD * OUT_DIM) / 4 / 256, 256>>>(value);

    dim3 g1(N_PAD / BN, B_ROWS / BM);        // (8, 128) = 1024 blocks
    gemm1_mma<<<g1, 256, SMEM_DYN>>>(bias);

    probs_kernel<<<B_ROWS, 256>>>();

    dim3 g2(OUT_DIM / BN, B_ROWS / BM);      // (4, 128)
    gemm2_mma<<<g2, 256, SMEM_DYN>>>(out);

    if (out_size > B_ROWS * OUT_DIM)
        reduce_reg_kernel<<<1, 256>>>(out + (size_t)B_ROWS * OUT_DIM);
}